// round 15
// baseline (speedup 1.0000x reference)
#include <cuda_runtime.h>
#include <cuda_fp16.h>
#include <cstdint>

// ============================================================================
// AWQ int4 linear via fp16 mma.sync (m16n8k16, fp32 accumulate):
//   (1) merged prepass: DIRECT fragment-order tile construction.
//   (2) GEMM: PERSISTENT 296 CTAs (2/SM), 128x128 tiles, 8 warps (64x32),
//       k-chunk 64, 3-stage cp.async + per-stage mbarriers, producer
//       specialization by half-CTA, paired consumer waits, and CROSS-TILE
//       pipelining: chunks 0-1 of the next tile are prefetched during the
//       current tile's last chunks, so the pipeline never drains.
// out[m][n] = sum_k x[m][k]*W[n][k] + bias[n]
// W[n][k] = (q[n][k]*scales[g]+offsets[g])*inv_scale[k], g = n*32 + k/128
// M=8192, N=11008, K=4096.
// ============================================================================

#define IN_DIM   4096
#define OUT_DIM  11008
#define M_DIM    8192
#define BKC      64                    // k per pipeline stage
#define NKC      (IN_DIM / BKC)        // 64 k-chunks per tile
#define STAGES   3
#define TILE_U32 4096                  // one 128x64 fp16 operand tile (16KB)
#define STAGE_U32 (2 * TILE_U32)       // A tile then B tile (32KB)
#define STAGE_BYTES (STAGE_U32 * 4)
#define SMEM_BYTES (STAGES * STAGE_BYTES + 64)   // 96KB + barriers
#define MT_TILES  (M_DIM / 128)        // 64
#define NT_TILES  (OUT_DIM / 128)      // 86
#define W_TILES   (NT_TILES * NKC)     // 5504
#define X_TILES   (MT_TILES * NKC)     // 4096
#define TOTAL_T   (NT_TILES * MT_TILES)   // 5504 output tiles
#define GRIDSZ    296                  // 2 CTAs x 148 SMs, persistent

// Pre-tiled fp16 operands in fragment order (static scratch; no allocs).
__device__ uint32_t g_w[(size_t)W_TILES * TILE_U32];   // 90 MB
__device__ uint32_t g_x[(size_t)X_TILES * TILE_U32];   // 67 MB

__device__ __forceinline__ uint32_t smem_u32(const void* p) {
    uint32_t a;
    asm("{ .reg .u64 t; cvta.to.shared.u64 t, %1; cvt.u32.u64 %0, t; }"
        : "=r"(a) : "l"(p));
    return a;
}

__device__ __forceinline__ uint32_t pack_h2(float lo, float hi) {
    __half2 h = __floats2half2_rn(lo, hi);   // .x = lo half
    return *(uint32_t*)&h;
}

// ---- mbarrier / cp.async primitives ----
#define MBAR_INIT(a, c) \
    asm volatile("mbarrier.init.shared.b64 [%0], %1;" :: "r"(a), "r"(c) : "memory")
#define MBAR_ARRIVE(a) \
    asm volatile("mbarrier.arrive.shared.b64 _, [%0];" :: "r"(a) : "memory")
#define CP_MBAR_ARRIVE(a) \
    asm volatile("cp.async.mbarrier.arrive.noinc.shared.b64 [%0];" \
                 :: "r"(a) : "memory")
#define MBAR_WAIT(a, ph) do {                                                  \
    uint32_t _m = (a), _p = (uint32_t)(ph), _d;                                \
    asm volatile("{\n\t.reg .pred p;\n\t"                                      \
        "mbarrier.try_wait.parity.acquire.cta.shared::cta.b64 p, [%1], %2;\n\t"\
        "selp.b32 %0, 1, 0, p;\n\t}" : "=r"(_d) : "r"(_m), "r"(_p) : "memory");\
    if (!_d) {                                                                 \
        asm volatile("{\n\t.reg .pred P1;\n\t"                                 \
            "W%=:\n\t"                                                         \
            "mbarrier.try_wait.parity.acquire.cta.shared::cta.b64 P1, [%0], %1, 0x989680;\n\t" \
            "@P1 bra.uni D%=;\n\t"                                             \
            "bra.uni W%=;\n\t"                                                 \
            "D%=:\n\t}" :: "r"(_m), "r"(_p) : "memory");                       \
    }                                                                          \
} while (0)

#define CP_ASYNC16(dst, src)                                                   \
    asm volatile("cp.async.cg.shared.global.L2::256B [%0], [%1], 16;"          \
                 :: "r"(dst), "l"(src) : "memory")

#define MMA_F16(c, a, b0v, b1v)                                                \
    asm volatile("mma.sync.aligned.m16n8k16.row.col.f32.f16.f16.f32 "          \
        "{%0,%1,%2,%3}, {%4,%5,%6,%7}, {%8,%9}, {%0,%1,%2,%3};"                \
        : "+f"((c)[0]), "+f"((c)[1]), "+f"((c)[2]), "+f"((c)[3])               \
        : "r"((a).x), "r"((a).y), "r"((a).z), "r"((a).w),                      \
          "r"(b0v), "r"(b1v))

// ============================================================================
// Merged prepass, direct construction, 128 threads x 8 uint4 per tile.
// ============================================================================
__global__ __launch_bounds__(128)
void prep_kernel(const int* __restrict__ packed,
                 const float* __restrict__ scales,
                 const float* __restrict__ offsets,
                 const float* __restrict__ inv,
                 const float* __restrict__ x) {
    const int tid = threadIdx.x;

    if (blockIdx.x < W_TILES) {
        const int tile = blockIdx.x;           // nT * NKC + kc
        const int nT = tile / NKC, kc = tile % NKC;
        const int kb = kc * 64;
        uint4* dst = (uint4*)(g_w + (size_t)tile * TILE_U32);
#pragma unroll
        for (int q = 0; q < 8; ++q) {
            const int u = q * 128 + tid;
            const int vec = u >> 5, lane = u & 31;
            const int wn = vec >> 3, ks = (vec >> 1) & 3, p = vec & 1;
            const int gid = lane >> 2, tig = lane & 3;
            const int kk0 = ks * 16 + tig * 2;
            const int kk1 = kk0 + 8;
            const int n0 = nT * 128 + wn * 32 + p * 16 + gid;
            const int n1 = n0 + 8;
            const int gr0 = (n0 << 5) + (kc >> 1);
            const int gr1 = (n1 << 5) + (kc >> 1);
            const float s0 = __ldg(scales + gr0), o0 = __ldg(offsets + gr0);
            const float s1 = __ldg(scales + gr1), o1 = __ldg(offsets + gr1);
            const int u00 = __ldg(packed + (size_t)n0 * 2048 + ((kb + kk0) >> 1));
            const int u01 = __ldg(packed + (size_t)n0 * 2048 + ((kb + kk1) >> 1));
            const int u10 = __ldg(packed + (size_t)n1 * 2048 + ((kb + kk0) >> 1));
            const int u11 = __ldg(packed + (size_t)n1 * 2048 + ((kb + kk1) >> 1));
            const float2 i0 = *(const float2*)(inv + kb + kk0);
            const float2 i1 = *(const float2*)(inv + kb + kk1);
            uint4 o;
            o.x = pack_h2(fmaf((float)(u00 & 15), s0, o0) * i0.x,
                          fmaf((float)((u00 >> 4) & 15), s0, o0) * i0.y);
            o.y = pack_h2(fmaf((float)(u01 & 15), s0, o0) * i1.x,
                          fmaf((float)((u01 >> 4) & 15), s0, o0) * i1.y);
            o.z = pack_h2(fmaf((float)(u10 & 15), s1, o1) * i0.x,
                          fmaf((float)((u10 >> 4) & 15), s1, o1) * i0.y);
            o.w = pack_h2(fmaf((float)(u11 & 15), s1, o1) * i1.x,
                          fmaf((float)((u11 >> 4) & 15), s1, o1) * i1.y);
            dst[u] = o;
        }
    } else {
        const int tile = blockIdx.x - W_TILES;   // mT * NKC + kc
        const int mT = tile / NKC, kc = tile % NKC;
        const int kb = kc * 64;
        uint4* dst = (uint4*)(g_x + (size_t)tile * TILE_U32);
#pragma unroll
        for (int q = 0; q < 8; ++q) {
            const int u = q * 128 + tid;
            const int vec = u >> 5, lane = u & 31;
            const int wm = vec >> 4, ks = (vec >> 2) & 3, b = vec & 3;
            const int gid = lane >> 2, tig = lane & 3;
            const int kk0 = ks * 16 + tig * 2;
            const int kk1 = kk0 + 8;
            const int m0 = mT * 128 + wm * 64 + b * 16 + gid;
            const int m1 = m0 + 8;
            const float2 x00 = *(const float2*)(x + (size_t)m0 * IN_DIM + kb + kk0);
            const float2 x01 = *(const float2*)(x + (size_t)m0 * IN_DIM + kb + kk1);
            const float2 x10 = *(const float2*)(x + (size_t)m1 * IN_DIM + kb + kk0);
            const float2 x11 = *(const float2*)(x + (size_t)m1 * IN_DIM + kb + kk1);
            uint4 o;
            o.x = pack_h2(x00.x, x00.y);
            o.y = pack_h2(x10.x, x10.y);
            o.z = pack_h2(x01.x, x01.y);
            o.w = pack_h2(x11.x, x11.y);
            dst[u] = o;
        }
    }
}

// ============================================================================
// Main GEMM: persistent CTAs, cross-tile pipelined, paired consumer waits.
// Tile order: t -> nT = t>>6, mT = t&63 (a wave shares one B panel; the whole
// A array stays L2-resident).
// ============================================================================
__device__ __forceinline__ void compute_chunk(
    const uint32_t* As, const uint32_t* Bs, int wm, int wn, int lane,
    float acc[4][4][4]) {
#pragma unroll
    for (int ks = 0; ks < 4; ++ks) {
        uint4 Af[4], Bf[2];
#pragma unroll
        for (int b = 0; b < 4; ++b)
            Af[b] = *(const uint4*)
                (As + ((wm * 16 + ks * 4 + b) * 32 + lane) * 4);
#pragma unroll
        for (int p = 0; p < 2; ++p)
            Bf[p] = *(const uint4*)
                (Bs + ((((wn * 4 + ks) * 2 + p) * 32) + lane) * 4);

#pragma unroll
        for (int b = 0; b < 4; ++b) {
            const uint4 a = Af[b];
#pragma unroll
            for (int nb = 0; nb < 4; ++nb) {
                const uint4 bf = Bf[nb >> 1];
                const uint32_t b0v = (nb & 1) ? bf.z : bf.x;
                const uint32_t b1v = (nb & 1) ? bf.w : bf.y;
                MMA_F16(acc[b][nb], a, b0v, b1v);
            }
        }
    }
}

__global__ __launch_bounds__(256, 2)
void awq_mma_gemm(const float* __restrict__ bias, float* __restrict__ out) {
    extern __shared__ uint32_t sm[];
    const int tid  = threadIdx.x;
    const int lane = tid & 31;
    const int wid  = tid >> 5;
    const int wm   = wid >> 2;      // m 64-half
    const int wn   = wid & 3;       // n 32-quarter

    const uint32_t sb  = smem_u32(sm);
    const uint32_t bar = sb + STAGES * STAGE_BYTES;   // full[s]=+8s, empty=+24+8s

    // producer role (fixed per thread): lower half copies A, upper half B.
    const int  pl  = tid & 127;
    const bool isA = tid < 128;
    const uint32_t dOff = (isA ? pl : 1024 + pl) * 16;

    if (tid == 0) {
#pragma unroll
        for (int s = 0; s < STAGES; ++s) {
            MBAR_INIT(bar + 8 * s, 256);       // full: one cp-arrive per thread
            MBAR_INIT(bar + 24 + 8 * s, 8);    // empty: one arrive per warp
        }
    }
    __syncthreads();

    // per-thread role base pointer for tile t
    auto base_for = [&](int tt) -> const uint32_t* {
        const int nT = tt >> 6, mT = tt & 63;
        return (isA ? g_x + (size_t)mT * (NKC * TILE_U32)
                    : g_w + (size_t)nT * (NKC * TILE_U32)) + pl * 4;
    };

    int t  = blockIdx.x;            // current tile
    int t2 = t + GRIDSZ;            // next tile (may be out of range)
    const uint32_t* pCur = base_for(t);
    const uint32_t* pNxt = (t2 < TOTAL_T) ? base_for(t2) : pCur;

    // ---- prologue: chunks 0,1 of first tile ----
#pragma unroll
    for (int s = 0; s < STAGES - 1; ++s) {
        const uint32_t dst = sb + s * STAGE_BYTES + dOff;
        const uint32_t* src = pCur + (size_t)s * TILE_U32;
#pragma unroll
        for (int i = 0; i < 8; ++i)
            CP_ASYNC16(dst + i * 2048, src + i * 512);
        CP_MBAR_ARRIVE(bar + 8 * s);
    }

    int scur = 0, fpar = 0;        // consumer cursor
    int ps = STAGES - 1, ep = 1;   // producer cursor
    bool first = true;

    for (;;) {
        float acc[4][4][4];
#pragma unroll
        for (int b = 0; b < 4; ++b)
#pragma unroll
            for (int nb = 0; nb < 4; ++nb)
#pragma unroll
                for (int i = 0; i < 4; ++i) acc[b][nb][i] = 0.0f;

#pragma unroll 1
        for (int kc = 0; kc < NKC; kc += 2) {
            int s1 = scur + 1, f1 = fpar;
            if (s1 == STAGES) { s1 = 0; f1 ^= 1; }

            // ---- produce chunk kc+2 (may belong to next tile) ----
            {
                const int j = kc + 2;
                const bool valid = (j < NKC) || (t2 < TOTAL_T);
                if (valid) {
                    if (!(first && kc == 0)) MBAR_WAIT(bar + 24 + 8 * ps, ep);
                    const uint32_t dst = sb + ps * STAGE_BYTES + dOff;
                    const uint32_t* src = (j < NKC)
                        ? pCur + (size_t)j * TILE_U32
                        : pNxt + (size_t)(j - NKC) * TILE_U32;
#pragma unroll
                    for (int i = 0; i < 8; ++i)
                        CP_ASYNC16(dst + i * 2048, src + i * 512);
                    CP_MBAR_ARRIVE(bar + 8 * ps);
                }
                if (++ps == STAGES) { ps = 0; ep ^= 1; }
            }

            // ---- one wait covers chunks kc, kc+1 (cp.async FIFO order) ----
            MBAR_WAIT(bar + 8 * s1, f1);

            // ---- compute chunk kc ----
            compute_chunk(sm + scur * STAGE_U32,
                          sm + scur * STAGE_U32 + TILE_U32, wm, wn, lane, acc);
            if (lane == 0) MBAR_ARRIVE(bar + 24 + 8 * scur);

            // ---- produce chunk kc+3 ----
            {
                const int j = kc + 3;
                const bool valid = (j < NKC) || (t2 < TOTAL_T);
                if (valid) {
                    MBAR_WAIT(bar + 24 + 8 * ps, ep);
                    const uint32_t dst = sb + ps * STAGE_BYTES + dOff;
                    const uint32_t* src = (j < NKC)
                        ? pCur + (size_t)j * TILE_U32
                        : pNxt + (size_t)(j - NKC) * TILE_U32;
#pragma unroll
                    for (int i = 0; i < 8; ++i)
                        CP_ASYNC16(dst + i * 2048, src + i * 512);
                    CP_MBAR_ARRIVE(bar + 8 * ps);
                }
                if (++ps == STAGES) { ps = 0; ep ^= 1; }
            }

            // ---- compute chunk kc+1 ----
            compute_chunk(sm + s1 * STAGE_U32,
                          sm + s1 * STAGE_U32 + TILE_U32, wm, wn, lane, acc);
            if (lane == 0) MBAR_ARRIVE(bar + 24 + 8 * s1);

            scur = s1 + 1; fpar = f1;
            if (scur == STAGES) { scur = 0; fpar ^= 1; }
        }
        first = false;

        // ---- epilogue: bias + store for tile t ----
        {
            const int nT = t >> 6, mT = t & 63;
            const int gid = lane >> 2, tig = lane & 3;
            const int m0 = mT * 128 + wm * 64;
            const int n0 = nT * 128 + wn * 32;
#pragma unroll
            for (int nb = 0; nb < 4; ++nb) {
                const int n = n0 + nb * 8 + tig * 2;
                const float2 bv = *(const float2*)(bias + n);
#pragma unroll
                for (int b = 0; b < 4; ++b) {
                    const int mA = m0 + b * 16 + gid;
                    float2 v0, v1;
                    v0.x = acc[b][nb][0] + bv.x;
                    v0.y = acc[b][nb][1] + bv.y;
                    v1.x = acc[b][nb][2] + bv.x;
                    v1.y = acc[b][nb][3] + bv.y;
                    *(float2*)(out + (size_t)mA * OUT_DIM + n) = v0;
                    *(float2*)(out + (size_t)(mA + 8) * OUT_DIM + n) = v1;
                }
            }
        }

        // ---- advance to next tile ----
        t = t2;
        if (t >= TOTAL_T) break;
        pCur = pNxt;
        t2 = t + GRIDSZ;
        if (t2 < TOTAL_T) pNxt = base_for(t2);
    }
}

// ============================================================================
extern "C" void kernel_launch(void* const* d_in, const int* in_sizes, int n_in,
                              void* d_out, int out_size) {
    const float* x         = (const float*)d_in[0];
    const int*   packed    = (const int*)  d_in[1];
    const float* scales    = (const float*)d_in[2];
    const float* offsets   = (const float*)d_in[3];
    const float* inv_scale = (const float*)d_in[4];
    const float* bias      = (const float*)d_in[5];
    float*       out       = (float*)d_out;

    static bool attr_set = false;
    if (!attr_set) {
        cudaFuncSetAttribute(awq_mma_gemm,
                             cudaFuncAttributeMaxDynamicSharedMemorySize,
                             SMEM_BYTES);
        attr_set = true;
    }

    prep_kernel<<<W_TILES + X_TILES, 128>>>(packed, scales, offsets,
                                            inv_scale, x);

    awq_mma_gemm<<<GRIDSZ, 256, SMEM_BYTES>>>(bias, out);
}

// round 16
// speedup vs baseline: 1.0444x; 1.0444x over previous
#include <cuda_runtime.h>
#include <cuda_fp16.h>
#include <cstdint>

// ============================================================================
// AWQ int4 linear via fp16 mma.sync (m16n8k16, fp32 accumulate):
//   (1) merged prepass: DIRECT fragment-order tile construction, tig-paired
//       (2 uint4 outputs per thread-step -> wide loads, half the LDG/STG).
//   (2) GEMM (R13, best config): 128x128 CTA tiles, 8 warps (warp 64x32),
//       k-chunk 64, 3-stage cp.async + per-stage mbarriers, producer
//       specialization by half-CTA, paired consumer waits, 2 CTAs/SM,
//       launch-order supertile raster (8 nT x 32 mT).
// out[m][n] = sum_k x[m][k]*W[n][k] + bias[n]
// W[n][k] = (q[n][k]*scales[g]+offsets[g])*inv_scale[k], g = n*32 + k/128
// M=8192, N=11008, K=4096.
// ============================================================================

#define IN_DIM   4096
#define OUT_DIM  11008
#define M_DIM    8192
#define BKC      64                    // k per pipeline stage
#define NKC      (IN_DIM / BKC)        // 64 k-chunks (even -> clean pairs)
#define STAGES   3
#define TILE_U32 4096                  // one 128x64 fp16 operand tile (16KB)
#define STAGE_U32 (2 * TILE_U32)       // A tile then B tile (32KB)
#define STAGE_BYTES (STAGE_U32 * 4)
#define SMEM_BYTES (STAGES * STAGE_BYTES + 64)   // 96KB + barriers
#define MT_TILES  (M_DIM / 128)        // 64
#define NT_TILES  (OUT_DIM / 128)      // 86
#define W_TILES   (NT_TILES * NKC)     // 5504
#define X_TILES   (MT_TILES * NKC)     // 4096

// Pre-tiled fp16 operands in fragment order (static scratch; no allocs).
__device__ uint32_t g_w[(size_t)W_TILES * TILE_U32];   // 90 MB
__device__ uint32_t g_x[(size_t)X_TILES * TILE_U32];   // 67 MB

__device__ __forceinline__ uint32_t smem_u32(const void* p) {
    uint32_t a;
    asm("{ .reg .u64 t; cvta.to.shared.u64 t, %1; cvt.u32.u64 %0, t; }"
        : "=r"(a) : "l"(p));
    return a;
}

__device__ __forceinline__ uint32_t pack_h2(float lo, float hi) {
    __half2 h = __floats2half2_rn(lo, hi);   // .x = lo half
    return *(uint32_t*)&h;
}

// ---- mbarrier / cp.async primitives ----
#define MBAR_INIT(a, c) \
    asm volatile("mbarrier.init.shared.b64 [%0], %1;" :: "r"(a), "r"(c) : "memory")
#define MBAR_ARRIVE(a) \
    asm volatile("mbarrier.arrive.shared.b64 _, [%0];" :: "r"(a) : "memory")
#define CP_MBAR_ARRIVE(a) \
    asm volatile("cp.async.mbarrier.arrive.noinc.shared.b64 [%0];" \
                 :: "r"(a) : "memory")
#define MBAR_WAIT(a, ph) do {                                                  \
    uint32_t _m = (a), _p = (uint32_t)(ph), _d;                                \
    asm volatile("{\n\t.reg .pred p;\n\t"                                      \
        "mbarrier.try_wait.parity.acquire.cta.shared::cta.b64 p, [%1], %2;\n\t"\
        "selp.b32 %0, 1, 0, p;\n\t}" : "=r"(_d) : "r"(_m), "r"(_p) : "memory");\
    if (!_d) {                                                                 \
        asm volatile("{\n\t.reg .pred P1;\n\t"                                 \
            "W%=:\n\t"                                                         \
            "mbarrier.try_wait.parity.acquire.cta.shared::cta.b64 P1, [%0], %1, 0x989680;\n\t" \
            "@P1 bra.uni D%=;\n\t"                                             \
            "bra.uni W%=;\n\t"                                                 \
            "D%=:\n\t}" :: "r"(_m), "r"(_p) : "memory");                       \
    }                                                                          \
} while (0)

#define CP_ASYNC16(dst, src)                                                   \
    asm volatile("cp.async.cg.shared.global.L2::256B [%0], [%1], 16;"          \
                 :: "r"(dst), "l"(src) : "memory")

#define MMA_F16(c, a, b0v, b1v)                                                \
    asm volatile("mma.sync.aligned.m16n8k16.row.col.f32.f16.f16.f32 "          \
        "{%0,%1,%2,%3}, {%4,%5,%6,%7}, {%8,%9}, {%0,%1,%2,%3};"                \
        : "+f"((c)[0]), "+f"((c)[1]), "+f"((c)[2]), "+f"((c)[3])               \
        : "r"((a).x), "r"((a).y), "r"((a).z), "r"((a).w),                      \
          "r"(b0v), "r"(b1v))

// ============================================================================
// Merged prepass, direct construction, tig-paired: 128 threads x 4 steps,
// each step builds 2 consecutive uint4 fragment units.
// Pair index pi: vec = pi>>4, r = pi&15, gid = r>>1, tigh = r&1.
// Output uint4 indices u0 = vec*32 + gid*4 + tigh*2, u1 = u0+1.
// ============================================================================
__global__ __launch_bounds__(128)
void prep_kernel(const int* __restrict__ packed,
                 const float* __restrict__ scales,
                 const float* __restrict__ offsets,
                 const float* __restrict__ inv,
                 const float* __restrict__ x) {
    const int tid = threadIdx.x;

    if (blockIdx.x < W_TILES) {
        const int tile = blockIdx.x;           // nT * NKC + kc
        const int nT = tile / NKC, kc = tile % NKC;
        const int kb = kc * 64;
        uint4* dst = (uint4*)(g_w + (size_t)tile * TILE_U32);
#pragma unroll
        for (int q = 0; q < 4; ++q) {
            const int pi = q * 128 + tid;
            const int vec = pi >> 4, r = pi & 15;
            const int gid = r >> 1, tigh = r & 1;
            const int wn = vec >> 3, ks = (vec >> 1) & 3, p = vec & 1;
            const int kk0 = ks * 16 + tigh * 4;    // covers kk0..kk0+3
            const int kk1 = kk0 + 8;
            const int n0 = nT * 128 + wn * 32 + p * 16 + gid;
            const int n1 = n0 + 8;
            const int gr0 = (n0 << 5) + (kc >> 1);
            const int gr1 = (n1 << 5) + (kc >> 1);
            const float s0 = __ldg(scales + gr0), o0 = __ldg(offsets + gr0);
            const float s1 = __ldg(scales + gr1), o1 = __ldg(offsets + gr1);
            // int2 loads: .x covers (kk,kk+1), .y covers (kk+2,kk+3)
            const int2 pA0 = *(const int2*)(packed + (size_t)n0 * 2048 + ((kb + kk0) >> 1));
            const int2 pA1 = *(const int2*)(packed + (size_t)n0 * 2048 + ((kb + kk1) >> 1));
            const int2 pB0 = *(const int2*)(packed + (size_t)n1 * 2048 + ((kb + kk0) >> 1));
            const int2 pB1 = *(const int2*)(packed + (size_t)n1 * 2048 + ((kb + kk1) >> 1));
            const float4 i0 = *(const float4*)(inv + kb + kk0);
            const float4 i1 = *(const float4*)(inv + kb + kk1);

            uint4 oA, oB;   // outputs for tig = tigh*2 and tigh*2+1
            oA.x = pack_h2(fmaf((float)(pA0.x & 15), s0, o0) * i0.x,
                           fmaf((float)((pA0.x >> 4) & 15), s0, o0) * i0.y);
            oB.x = pack_h2(fmaf((float)(pA0.y & 15), s0, o0) * i0.z,
                           fmaf((float)((pA0.y >> 4) & 15), s0, o0) * i0.w);
            oA.y = pack_h2(fmaf((float)(pA1.x & 15), s0, o0) * i1.x,
                           fmaf((float)((pA1.x >> 4) & 15), s0, o0) * i1.y);
            oB.y = pack_h2(fmaf((float)(pA1.y & 15), s0, o0) * i1.z,
                           fmaf((float)((pA1.y >> 4) & 15), s0, o0) * i1.w);
            oA.z = pack_h2(fmaf((float)(pB0.x & 15), s1, o1) * i0.x,
                           fmaf((float)((pB0.x >> 4) & 15), s1, o1) * i0.y);
            oB.z = pack_h2(fmaf((float)(pB0.y & 15), s1, o1) * i0.z,
                           fmaf((float)((pB0.y >> 4) & 15), s1, o1) * i0.w);
            oA.w = pack_h2(fmaf((float)(pB1.x & 15), s1, o1) * i1.x,
                           fmaf((float)((pB1.x >> 4) & 15), s1, o1) * i1.y);
            oB.w = pack_h2(fmaf((float)(pB1.y & 15), s1, o1) * i1.z,
                           fmaf((float)((pB1.y >> 4) & 15), s1, o1) * i1.w);

            const int u0 = vec * 32 + gid * 4 + tigh * 2;
            dst[u0]     = oA;
            dst[u0 + 1] = oB;
        }
    } else {
        const int tile = blockIdx.x - W_TILES;   // mT * NKC + kc
        const int mT = tile / NKC, kc = tile % NKC;
        const int kb = kc * 64;
        uint4* dst = (uint4*)(g_x + (size_t)tile * TILE_U32);
#pragma unroll
        for (int q = 0; q < 4; ++q) {
            const int pi = q * 128 + tid;
            const int vec = pi >> 4, r = pi & 15;
            const int gid = r >> 1, tigh = r & 1;
            const int wm = vec >> 4, ks = (vec >> 2) & 3, b = vec & 3;
            const int kk0 = ks * 16 + tigh * 4;
            const int kk1 = kk0 + 8;
            const int m0 = mT * 128 + wm * 64 + b * 16 + gid;
            const int m1 = m0 + 8;
            const float4 xA0 = *(const float4*)(x + (size_t)m0 * IN_DIM + kb + kk0);
            const float4 xA1 = *(const float4*)(x + (size_t)m0 * IN_DIM + kb + kk1);
            const float4 xB0 = *(const float4*)(x + (size_t)m1 * IN_DIM + kb + kk0);
            const float4 xB1 = *(const float4*)(x + (size_t)m1 * IN_DIM + kb + kk1);

            uint4 oA, oB;
            oA.x = pack_h2(xA0.x, xA0.y);
            oB.x = pack_h2(xA0.z, xA0.w);
            oA.y = pack_h2(xB0.x, xB0.y);
            oB.y = pack_h2(xB0.z, xB0.w);
            oA.z = pack_h2(xA1.x, xA1.y);
            oB.z = pack_h2(xA1.z, xA1.w);
            oA.w = pack_h2(xB1.x, xB1.y);
            oB.w = pack_h2(xB1.z, xB1.w);

            const int u0 = vec * 32 + gid * 4 + tigh * 2;
            dst[u0]     = oA;
            dst[u0 + 1] = oB;
        }
    }
}

// ============================================================================
// Main GEMM: 128x128 per CTA, 256 threads, warp 64x32, mbarrier pipeline,
// producer specialization, paired consumer waits. (R13, unchanged)
// ============================================================================
__device__ __forceinline__ void compute_chunk(
    const uint32_t* As, const uint32_t* Bs, int wm, int wn, int lane,
    float acc[4][4][4]) {
#pragma unroll
    for (int ks = 0; ks < 4; ++ks) {
        uint4 Af[4], Bf[2];
#pragma unroll
        for (int b = 0; b < 4; ++b)
            Af[b] = *(const uint4*)
                (As + ((wm * 16 + ks * 4 + b) * 32 + lane) * 4);
#pragma unroll
        for (int p = 0; p < 2; ++p)
            Bf[p] = *(const uint4*)
                (Bs + ((((wn * 4 + ks) * 2 + p) * 32) + lane) * 4);

#pragma unroll
        for (int b = 0; b < 4; ++b) {
            const uint4 a = Af[b];
#pragma unroll
            for (int nb = 0; nb < 4; ++nb) {
                const uint4 bf = Bf[nb >> 1];
                const uint32_t b0v = (nb & 1) ? bf.z : bf.x;
                const uint32_t b1v = (nb & 1) ? bf.w : bf.y;
                MMA_F16(acc[b][nb], a, b0v, b1v);
            }
        }
    }
}

__global__ __launch_bounds__(256, 2)
void awq_mma_gemm(const float* __restrict__ bias, float* __restrict__ out) {
    extern __shared__ uint32_t sm[];
    const int tid  = threadIdx.x;
    const int lane = tid & 31;
    const int wid  = tid >> 5;
    const int wm   = wid >> 2;      // m 64-half
    const int wn   = wid & 3;       // n 32-quarter

    // supertile raster: grid(256, 22); x: 8 nT x 32 mT inside a supertile
    const int sc  = blockIdx.y % 11;
    const int smr = blockIdx.y / 11;
    const int nT  = sc * 8 + (blockIdx.x & 7);
    const int mT  = smr * 32 + (blockIdx.x >> 3);
    if (nT >= NT_TILES) return;

    const uint32_t* aSrc = g_x + (size_t)mT * NKC * TILE_U32;
    const uint32_t* bSrc = g_w + (size_t)nT * NKC * TILE_U32;
    const uint32_t sb  = smem_u32(sm);
    const uint32_t bar = sb + STAGES * STAGE_BYTES;   // full[s]=+8s, empty=+24+8s

    // producer role (fixed per thread): lower half copies A, upper half B.
    const int   pl      = tid & 127;
    const bool  isA     = tid < 128;
    const uint32_t* gBase = (isA ? aSrc : bSrc) + pl * 4;   // + chunk*TILE_U32
    const uint32_t dOff = (isA ? pl : 1024 + pl) * 16;

    if (tid == 0) {
#pragma unroll
        for (int s = 0; s < STAGES; ++s) {
            MBAR_INIT(bar + 8 * s, 256);       // full: one cp-arrive per thread
            MBAR_INIT(bar + 24 + 8 * s, 8);    // empty: one arrive per warp
        }
    }
    __syncthreads();

    float acc[4][4][4];
#pragma unroll
    for (int b = 0; b < 4; ++b)
#pragma unroll
        for (int nb = 0; nb < 4; ++nb)
#pragma unroll
            for (int i = 0; i < 4; ++i) acc[b][nb][i] = 0.0f;

    // ---- prologue: fill stages 0..STAGES-2 (chunks 0,1) ----
#pragma unroll
    for (int s = 0; s < STAGES - 1; ++s) {
        const uint32_t dst = sb + s * STAGE_BYTES + dOff;
        const uint32_t* src = gBase + (size_t)s * TILE_U32;
#pragma unroll
        for (int i = 0; i < 8; ++i)
            CP_ASYNC16(dst + i * 2048, src + i * 512);
        CP_MBAR_ARRIVE(bar + 8 * s);
    }

    int scur = 0, fpar = 0;        // consumer cursor for chunk kc
    int ps = STAGES - 1, ep = 1;   // producer cursor (advances 1 per chunk)
#pragma unroll 1
    for (int kc = 0; kc < NKC; kc += 2) {
        // cursor for kc+1
        int s1 = scur + 1, f1 = fpar;
        if (s1 == STAGES) { s1 = 0; f1 ^= 1; }

        // ---- produce chunk kc+2 into stage ps ----
        {
            const int pc = kc + 2;
            if (pc < NKC) {
                if (pc >= STAGES) MBAR_WAIT(bar + 24 + 8 * ps, ep);
                const uint32_t dst = sb + ps * STAGE_BYTES + dOff;
                const uint32_t* src = gBase + (size_t)pc * TILE_U32;
#pragma unroll
                for (int i = 0; i < 8; ++i)
                    CP_ASYNC16(dst + i * 2048, src + i * 512);
                CP_MBAR_ARRIVE(bar + 8 * ps);
            }
            if (++ps == STAGES) { ps = 0; ep ^= 1; }
        }

        // ---- single wait covers chunks kc and kc+1 (cp.async FIFO order) ----
        MBAR_WAIT(bar + 8 * s1, f1);

        // ---- compute chunk kc ----
        compute_chunk(sm + scur * STAGE_U32, sm + scur * STAGE_U32 + TILE_U32,
                      wm, wn, lane, acc);
        if (lane == 0) MBAR_ARRIVE(bar + 24 + 8 * scur);

        // ---- produce chunk kc+3 into stage ps (needs empty(kc): just arrived) ----
        {
            const int pc = kc + 3;
            if (pc < NKC) {
                MBAR_WAIT(bar + 24 + 8 * ps, ep);
                const uint32_t dst = sb + ps * STAGE_BYTES + dOff;
                const uint32_t* src = gBase + (size_t)pc * TILE_U32;
#pragma unroll
                for (int i = 0; i < 8; ++i)
                    CP_ASYNC16(dst + i * 2048, src + i * 512);
                CP_MBAR_ARRIVE(bar + 8 * ps);
            }
            if (++ps == STAGES) { ps = 0; ep ^= 1; }
        }

        // ---- compute chunk kc+1 ----
        compute_chunk(sm + s1 * STAGE_U32, sm + s1 * STAGE_U32 + TILE_U32,
                      wm, wn, lane, acc);
        if (lane == 0) MBAR_ARRIVE(bar + 24 + 8 * s1);

        // advance consumer cursor past the pair
        scur = s1 + 1; fpar = f1;
        if (scur == STAGES) { scur = 0; fpar ^= 1; }
    }

    // ---- epilogue: bias + store ----
    const int gid = lane >> 2, tig = lane & 3;
    const int m0 = mT * 128 + wm * 64;
    const int n0 = nT * 128 + wn * 32;
#pragma unroll
    for (int nb = 0; nb < 4; ++nb) {
        const int n = n0 + nb * 8 + tig * 2;
        const float2 bv = *(const float2*)(bias + n);
#pragma unroll
        for (int b = 0; b < 4; ++b) {
            const int mA = m0 + b * 16 + gid;
            float2 v0, v1;
            v0.x = acc[b][nb][0] + bv.x;
            v0.y = acc[b][nb][1] + bv.y;
            v1.x = acc[b][nb][2] + bv.x;
            v1.y = acc[b][nb][3] + bv.y;
            *(float2*)(out + (size_t)mA * OUT_DIM + n) = v0;
            *(float2*)(out + (size_t)(mA + 8) * OUT_DIM + n) = v1;
        }
    }
}

// ============================================================================
extern "C" void kernel_launch(void* const* d_in, const int* in_sizes, int n_in,
                              void* d_out, int out_size) {
    const float* x         = (const float*)d_in[0];
    const int*   packed    = (const int*)  d_in[1];
    const float* scales    = (const float*)d_in[2];
    const float* offsets   = (const float*)d_in[3];
    const float* inv_scale = (const float*)d_in[4];
    const float* bias      = (const float*)d_in[5];
    float*       out       = (float*)d_out;

    static bool attr_set = false;
    if (!attr_set) {
        cudaFuncSetAttribute(awq_mma_gemm,
                             cudaFuncAttributeMaxDynamicSharedMemorySize,
                             SMEM_BYTES);
        attr_set = true;
    }

    prep_kernel<<<W_TILES + X_TILES, 128>>>(packed, scales, offsets,
                                            inv_scale, x);

    dim3 grid(256, 22);   // 8 nT x 32 mT supertiles; 2 superrows x 11 supercols
    awq_mma_gemm<<<grid, 256, SMEM_BYTES>>>(bias, out);
}